// round 10
// baseline (speedup 1.0000x reference)
#include <cuda_runtime.h>
#include <cuda.h>
#include <cuda_bf16.h>
#include <math.h>
#include <stdint.h>
#include <dlfcn.h>

// ---------------- problem constants ----------------
#define BATCH 512
#define HH 14
#define WW 14
#define DIN 512
#define EDIM 64
#define KCODES 256
#define NPIX (BATCH*HH*WW)          // 100352
#define NTOK (BATCH*4)              // 2048
#define H1 128                      // 2*EDIM

#define OUT_PPL ((size_t)NPIX*DIN)
#define OUT_CMT (OUT_PPL+1)
#define OUT_IDX (OUT_PPL+2)

// ---------------- scratch (static device memory; no allocations) ----------------
__device__ float g_H[(size_t)NPIX*H1];      // gelu(delta@W1+b1)
__device__ float g_Hbar[NTOK*H1];
__device__ float g_S[NTOK*DIN];
__device__ int   g_idx[NTOK];
__device__ int   g_counts[KCODES];
__device__ float g_loss;
// W1^T split into bf16 hi/lo: [n=128][k=512]  (fallback path)
__device__ __nv_bfloat16 g_w1t_hi[H1*DIN];
__device__ __nv_bfloat16 g_w1t_lo[H1*DIN];
// W1^T pre-tiled, SW128-swizzled, chunk-major: [tensor(hi,lo)][chunk 8][16384 B]
__device__ __align__(1024) unsigned char g_w1B[2][8][16384];

__device__ __forceinline__ float gelu_exact(float x) {
    return 0.5f * x * (1.0f + erff(x * 0.70710678118654752440f));
}

__device__ __forceinline__ uint32_t smem_u32(const void* p) {
    uint32_t a;
    asm("{ .reg .u64 t; cvta.to.shared.u64 t, %1; cvt.u32.u64 %0, t; }" : "=r"(a) : "l"(p));
    return a;
}

// baseline-PTX tensor ops (valid on plain sm_103 — no 'a' features)
__device__ __forceinline__ void ldsm_x4(uint32_t* r, uint32_t addr) {
    asm volatile("ldmatrix.sync.aligned.m8n8.x4.shared.b16 {%0,%1,%2,%3}, [%4];"
                 : "=r"(r[0]), "=r"(r[1]), "=r"(r[2]), "=r"(r[3]) : "r"(addr));
}
__device__ __forceinline__ void mma_bf16(float* d, const uint32_t* a, const uint32_t* b) {
    asm volatile("mma.sync.aligned.m16n8k16.row.col.f32.bf16.bf16.f32 "
                 "{%0,%1,%2,%3}, {%4,%5,%6,%7}, {%8,%9}, {%0,%1,%2,%3};"
                 : "+f"(d[0]), "+f"(d[1]), "+f"(d[2]), "+f"(d[3])
                 : "r"(a[0]), "r"(a[1]), "r"(a[2]), "r"(a[3]), "r"(b[0]), "r"(b[1]));
}
__device__ __forceinline__ uint32_t pk_bf16(__nv_bfloat16 a, __nv_bfloat16 b) {
    return (uint32_t)__bfloat16_as_ushort(a) | ((uint32_t)__bfloat16_as_ushort(b) << 16);
}
__device__ __forceinline__ void cp_async16(uint32_t dst, const void* src) {
    asm volatile("cp.async.ca.shared.global [%0], [%1], 16;" :: "r"(dst), "l"(src) : "memory");
}
#define CP_COMMIT()  asm volatile("cp.async.commit_group;" ::: "memory")
#define CP_WAIT0()   asm volatile("cp.async.wait_group 0;" ::: "memory")

// mbarrier (sm_90 baseline)
#define MBAR_INIT(a, c)   asm volatile("mbarrier.init.shared.b64 [%0], %1;" :: "r"(a), "r"((uint32_t)(c)) : "memory")
#define MBAR_EXPECT_TX(a, n) asm volatile("mbarrier.arrive.expect_tx.shared.b64 _, [%0], %1;" :: "r"(a), "r"((uint32_t)(n)) : "memory")
__device__ __forceinline__ void mbar_wait(uint32_t mbar, uint32_t parity) {
    asm volatile(
        "{\n\t.reg .pred P;\n\t"
        "WL%=:\n\t"
        "mbarrier.try_wait.parity.acquire.cta.shared::cta.b64 P, [%0], %1, 0x989680;\n\t"
        "@P bra WD%=;\n\t"
        "bra WL%=;\n\t"
        "WD%=:\n\t}"
        :: "r"(mbar), "r"(parity) : "memory");
}
// TMA / bulk (sm_90 baseline; shared::cluster dst form)
__device__ __forceinline__ void tma_2d(uint32_t dst, const CUtensorMap* m, int x, int y, uint32_t bar) {
    asm volatile("cp.async.bulk.tensor.2d.shared::cluster.global.tile.mbarrier::complete_tx::bytes "
                 "[%0], [%1, {%2, %3}], [%4];"
                 :: "r"(dst), "l"(m), "r"(x), "r"(y), "r"(bar) : "memory");
}
__device__ __forceinline__ void bulk_1d(uint32_t dst, const void* src, uint32_t bytes, uint32_t bar) {
    asm volatile("cp.async.bulk.shared::cluster.global.mbarrier::complete_tx::bytes [%0], [%1], %2, [%3];"
                 :: "r"(dst), "l"(src), "r"(bytes), "r"(bar) : "memory");
}

#define SWZ(off) ((off) ^ (((off) >> 3) & 0x70))

// ---------------- kernel 0: zero accumulators ----------------
__global__ void k_init() {
    int t = threadIdx.x;
    if (t < KCODES) g_counts[t] = 0;
    if (t == 0) g_loss = 0.0f;
}

// ---------------- kernel 0b: pre-split W1^T into bf16 hi/lo (+ swizzled tiles) ----------------
__global__ __launch_bounds__(256) void k_prep(const float* __restrict__ w1) {
    int idx = blockIdx.x * 256 + threadIdx.x;   // over 512*128
    int k = idx >> 7, n = idx & 127;
    float v = w1[idx];
    __nv_bfloat16 hi = __float2bfloat16(v);
    __nv_bfloat16 lo = __float2bfloat16(v - __bfloat162float(hi));
    g_w1t_hi[n * DIN + k] = hi;
    g_w1t_lo[n * DIN + k] = lo;
    int chunk = k >> 6, kk = k & 63;
    uint32_t off = SWZ((uint32_t)(n * 128 + kk * 2));
    *(__nv_bfloat16*)(&g_w1B[0][chunk][off]) = hi;
    *(__nv_bfloat16*)(&g_w1B[1][chunk][off]) = lo;
}

// ---------------- kernel 1 (TMA): delta -> split-bf16 HMMA GEMM -> GELU ----------------
// smem map (bytes):
//   [0..131071]        A fp32 stage: buf{0,1} x {t0,t1} x 32768
//   [131072..196607]   B bf16 tiles: buf{0,1} x {hi,lo} x 16384  (SW128 swizzled)
//   [196608..229375]   A bf16 tiles: hi 16384, lo 16384          (SW128 swizzled)
//   [229376..]         barriers: barA[2], barB[2]
#define TST_T0(buf) ((uint32_t)(buf)*65536u)
#define TST_T1(buf) ((uint32_t)(buf)*65536u + 32768u)
#define BST_HI(buf) (131072u + (uint32_t)(buf)*32768u)
#define BST_LO(buf) (131072u + (uint32_t)(buf)*32768u + 16384u)
#define ATI_HI 196608u
#define ATI_LO 212992u
#define BAR_A(buf) (229376u + (uint32_t)(buf)*8u)
#define BAR_B(buf) (229408u + (uint32_t)(buf)*8u)
#define ENC2_SM_BYTES (229376 + 64)

__global__ __launch_bounds__(256, 1) void k_enc1_tma(const __grid_constant__ CUtensorMap mT0,
                                                     const __grid_constant__ CUtensorMap mT1,
                                                     const float* __restrict__ b1) {
    extern __shared__ char sm[];
    const uint32_t smb = smem_u32(sm);
    const int tid = threadIdx.x;
    const int wid = tid >> 5, l = tid & 31;
    const int wm = wid & 3, wn = wid >> 2;
    const int p0 = blockIdx.x * 128;

    if (tid == 0) {
#pragma unroll
        for (int b = 0; b < 2; b++) { MBAR_INIT(smb + BAR_A(b), 1); MBAR_INIT(smb + BAR_B(b), 1); }
    }
    __syncthreads();

    // prologue: issue chunk 0 into buf 0
    if (tid == 0) {
        MBAR_EXPECT_TX(smb + BAR_A(0), 65536u);
        tma_2d(smb + TST_T0(0), &mT0, 0, p0, smb + BAR_A(0));
        tma_2d(smb + TST_T1(0), &mT1, 0, p0, smb + BAR_A(0));
        MBAR_EXPECT_TX(smb + BAR_B(0), 32768u);
        bulk_1d(smb + BST_HI(0), &g_w1B[0][0][0], 16384u, smb + BAR_B(0));
        bulk_1d(smb + BST_LO(0), &g_w1B[1][0][0], 16384u, smb + BAR_B(0));
    }

    float acc[2][8][4];
#pragma unroll
    for (int rt = 0; rt < 2; rt++)
#pragma unroll
        for (int nt = 0; nt < 8; nt++)
#pragma unroll
            for (int q = 0; q < 4; q++) acc[rt][nt][q] = 0.0f;

    const uint32_t a_row = (uint32_t)(wm * 32 + (l & 15));
    const uint32_t a_kof = (uint32_t)((l >> 4) * 16);
    const uint32_t b_row4 = (uint32_t)(wn * 64 + ((l >> 4) << 3) + (l & 7));
    const uint32_t b_k4   = (uint32_t)(((l >> 3) & 1) * 16);

    for (int c = 0; c < 8; c++) {
        const int buf = c & 1;
        __syncthreads();    // all prior-chunk consumers done (stage buf^1 free, A tiles free)

        if (tid == 0 && c < 7) {
            const int nb = buf ^ 1;
            MBAR_EXPECT_TX(smb + BAR_A(nb), 65536u);
            tma_2d(smb + TST_T0(nb), &mT0, (c + 1) * 64, p0, smb + BAR_A(nb));
            tma_2d(smb + TST_T1(nb), &mT1, (c + 1) * 64, p0, smb + BAR_A(nb));
            MBAR_EXPECT_TX(smb + BAR_B(nb), 32768u);
            bulk_1d(smb + BST_HI(nb), &g_w1B[0][c + 1][0], 16384u, smb + BAR_B(nb));
            bulk_1d(smb + BST_LO(nb), &g_w1B[1][c + 1][0], 16384u, smb + BAR_B(nb));
        }

        const uint32_t par = (uint32_t)((c >> 1) & 1);
        mbar_wait(smb + BAR_A(buf), par);
        mbar_wait(smb + BAR_B(buf), par);

        // convert: fp32 stage -> bf16 hi/lo A tiles (SW128)
#pragma unroll
        for (int it = 0; it < 8; it++) {
            int i = tid + it * 256;            // 2048 float4 groups
            int row = i >> 4, g = i & 15;
            uint32_t soff = (uint32_t)(row * 256 + g * 16);
            float4 v1 = *(const float4*)(sm + TST_T1(buf) + soff);
            float4 v0 = *(const float4*)(sm + TST_T0(buf) + soff);
            float d0 = v1.x - v0.x, d1 = v1.y - v0.y, d2 = v1.z - v0.z, d3 = v1.w - v0.w;
            __nv_bfloat16 h0 = __float2bfloat16(d0), h1 = __float2bfloat16(d1),
                          h2 = __float2bfloat16(d2), h3 = __float2bfloat16(d3);
            __nv_bfloat16 e0 = __float2bfloat16(d0 - __bfloat162float(h0));
            __nv_bfloat16 e1 = __float2bfloat16(d1 - __bfloat162float(h1));
            __nv_bfloat16 e2 = __float2bfloat16(d2 - __bfloat162float(h2));
            __nv_bfloat16 e3 = __float2bfloat16(d3 - __bfloat162float(h3));
            uint32_t toff = SWZ((uint32_t)(row * 128 + g * 8));
            *(uint2*)(sm + ATI_HI + toff) = make_uint2(pk_bf16(h0, h1), pk_bf16(h2, h3));
            *(uint2*)(sm + ATI_LO + toff) = make_uint2(pk_bf16(e0, e1), pk_bf16(e2, e3));
        }
        __syncthreads();

        // compute: 4 k16 steps
#pragma unroll
        for (int ks = 0; ks < 4; ks++) {
            uint32_t ahi[2][4], alo[2][4];
#pragma unroll
            for (int rt = 0; rt < 2; rt++) {
                uint32_t aoff = SWZ((a_row + rt * 16) * 128 + ks * 32 + a_kof);
                ldsm_x4(ahi[rt], smb + ATI_HI + aoff);
                ldsm_x4(alo[rt], smb + ATI_LO + aoff);
            }
#pragma unroll
            for (int ntp = 0; ntp < 4; ntp++) {
                uint32_t boff = SWZ((b_row4 + ntp * 16) * 128 + ks * 32 + b_k4);
                uint32_t bhi[4], blo[4];
                ldsm_x4(bhi, smb + BST_HI(buf) + boff);
                ldsm_x4(blo, smb + BST_LO(buf) + boff);
#pragma unroll
                for (int h = 0; h < 2; h++) {
                    int nt = ntp * 2 + h;
#pragma unroll
                    for (int rt = 0; rt < 2; rt++) {
                        mma_bf16(acc[rt][nt], ahi[rt], bhi + 2 * h);
                        mma_bf16(acc[rt][nt], ahi[rt], blo + 2 * h);
                        mma_bf16(acc[rt][nt], alo[rt], bhi + 2 * h);
                    }
                }
            }
        }
    }

    // epilogue: bias + exact GELU
    float2 bias[8];
#pragma unroll
    for (int nt = 0; nt < 8; nt++) {
        int cc = wn * 64 + nt * 8 + 2 * (l & 3);
        bias[nt] = make_float2(__ldg(&b1[cc]), __ldg(&b1[cc + 1]));
    }
#pragma unroll
    for (int rt = 0; rt < 2; rt++) {
        int r0 = p0 + wm * 32 + rt * 16 + (l >> 2);
#pragma unroll
        for (int nt = 0; nt < 8; nt++) {
            int cc = wn * 64 + nt * 8 + 2 * (l & 3);
            float2 o0, o1;
            o0.x = gelu_exact(acc[rt][nt][0] + bias[nt].x);
            o0.y = gelu_exact(acc[rt][nt][1] + bias[nt].y);
            o1.x = gelu_exact(acc[rt][nt][2] + bias[nt].x);
            o1.y = gelu_exact(acc[rt][nt][3] + bias[nt].y);
            *(float2*)&g_H[(size_t)r0 * H1 + cc]       = o0;
            *(float2*)&g_H[(size_t)(r0 + 8) * H1 + cc] = o1;
        }
    }
}

// ---------------- kernel 1 fallback (LDG staging, R9 version) ----------------
#define SM_AHI 0
#define SM_ALO (128*144)
#define SM_BHI (2*128*144)
#define SM_BLO (3*128*144)
#define ENC_SM_BYTES (4*128*144)

__global__ __launch_bounds__(256, 2) void k_enc1_ldg(const float* __restrict__ t0,
                                                     const float* __restrict__ t1,
                                                     const float* __restrict__ b1) {
    extern __shared__ char sm[];
    const uint32_t smb = smem_u32(sm);
    const int tid = threadIdx.x;
    const int wid = tid >> 5, l = tid & 31;
    const int wm = wid & 3, wn = wid >> 2;
    const int p0 = blockIdx.x * 128;

    float acc[2][8][4];
#pragma unroll
    for (int rt = 0; rt < 2; rt++)
#pragma unroll
        for (int nt = 0; nt < 8; nt++)
#pragma unroll
            for (int q = 0; q < 4; q++) acc[rt][nt][q] = 0.0f;

    const uint32_t a_row = (uint32_t)(wm * 32 + (l & 15));
    const uint32_t a_kof = (uint32_t)((l >> 4) * 16);
    const uint32_t b_row4 = (uint32_t)(wn * 64 + ((l >> 4) << 3) + (l & 7));
    const uint32_t b_k4   = (uint32_t)(((l >> 3) & 1) * 16);

    for (int c = 0; c < 8; c++) {
        const int kc = c * 64;
        if (c) __syncthreads();
#pragma unroll
        for (int it = 0; it < 4; it++) {
            int i = tid + it * 256;
            int n = i >> 3, g = i & 7;
            uint32_t off = (uint32_t)(n * 144 + g * 16);
            cp_async16(smb + SM_BHI + off, g_w1t_hi + n * DIN + kc + g * 8);
            cp_async16(smb + SM_BLO + off, g_w1t_lo + n * DIN + kc + g * 8);
        }
        CP_COMMIT();
#pragma unroll
        for (int half = 0; half < 4; half++) {
            float4 v1[2], v0[2];
            int rows[2], gs[2];
#pragma unroll
            for (int u = 0; u < 2; u++) {
                int i = tid + (half * 2 + u) * 256;
                rows[u] = i >> 4; gs[u] = i & 15;
                size_t gaddr = (size_t)(p0 + rows[u]) * DIN + kc + gs[u] * 4;
                v1[u] = *(const float4*)(t1 + gaddr);
                v0[u] = *(const float4*)(t0 + gaddr);
            }
#pragma unroll
            for (int u = 0; u < 2; u++) {
                float d0 = v1[u].x - v0[u].x, d1 = v1[u].y - v0[u].y,
                      d2 = v1[u].z - v0[u].z, d3 = v1[u].w - v0[u].w;
                __nv_bfloat16 h0 = __float2bfloat16(d0), h1 = __float2bfloat16(d1),
                              h2 = __float2bfloat16(d2), h3 = __float2bfloat16(d3);
                __nv_bfloat16 e0 = __float2bfloat16(d0 - __bfloat162float(h0));
                __nv_bfloat16 e1 = __float2bfloat16(d1 - __bfloat162float(h1));
                __nv_bfloat16 e2 = __float2bfloat16(d2 - __bfloat162float(h2));
                __nv_bfloat16 e3 = __float2bfloat16(d3 - __bfloat162float(h3));
                uint32_t off = (uint32_t)(rows[u] * 144 + gs[u] * 8);
                *(uint2*)(sm + SM_AHI + off) = make_uint2(pk_bf16(h0, h1), pk_bf16(h2, h3));
                *(uint2*)(sm + SM_ALO + off) = make_uint2(pk_bf16(e0, e1), pk_bf16(e2, e3));
            }
        }
        CP_WAIT0();
        __syncthreads();
#pragma unroll
        for (int ks = 0; ks < 4; ks++) {
            uint32_t ahi[2][4], alo[2][4];
#pragma unroll
            for (int rt = 0; rt < 2; rt++) {
                uint32_t aoff = (a_row + rt * 16) * 144 + ks * 32 + a_kof;
                ldsm_x4(ahi[rt], smb + SM_AHI + aoff);
                ldsm_x4(alo[rt], smb + SM_ALO + aoff);
            }
#pragma unroll
            for (int ntp = 0; ntp < 4; ntp++) {
                uint32_t boff = (b_row4 + ntp * 16) * 144 + ks * 32 + b_k4;
                uint32_t bhi[4], blo[4];
                ldsm_x4(bhi, smb + SM_BHI + boff);
                ldsm_x4(blo, smb + SM_BLO + boff);
#pragma unroll
                for (int h = 0; h < 2; h++) {
                    int nt = ntp * 2 + h;
#pragma unroll
                    for (int rt = 0; rt < 2; rt++) {
                        mma_bf16(acc[rt][nt], ahi[rt], bhi + 2 * h);
                        mma_bf16(acc[rt][nt], ahi[rt], blo + 2 * h);
                        mma_bf16(acc[rt][nt], alo[rt], bhi + 2 * h);
                    }
                }
            }
        }
    }

    float2 bias[8];
#pragma unroll
    for (int nt = 0; nt < 8; nt++) {
        int cc = wn * 64 + nt * 8 + 2 * (l & 3);
        bias[nt] = make_float2(__ldg(&b1[cc]), __ldg(&b1[cc + 1]));
    }
#pragma unroll
    for (int rt = 0; rt < 2; rt++) {
        int r0 = p0 + wm * 32 + rt * 16 + (l >> 2);
#pragma unroll
        for (int nt = 0; nt < 8; nt++) {
            int cc = wn * 64 + nt * 8 + 2 * (l & 3);
            float2 o0, o1;
            o0.x = gelu_exact(acc[rt][nt][0] + bias[nt].x);
            o0.y = gelu_exact(acc[rt][nt][1] + bias[nt].y);
            o1.x = gelu_exact(acc[rt][nt][2] + bias[nt].x);
            o1.y = gelu_exact(acc[rt][nt][3] + bias[nt].y);
            *(float2*)&g_H[(size_t)r0 * H1 + cc]       = o0;
            *(float2*)&g_H[(size_t)(r0 + 8) * H1 + cc] = o1;
        }
    }
}

// ---------------- kernel 2: 7x7 block-mean pooling ----------------
__global__ __launch_bounds__(128) void k_pool() {
    int t = blockIdx.x;
    int j = threadIdx.x;
    int b = t >> 2, g = t & 3, gy = g >> 1, gx = g & 1;
    float s = 0.0f;
#pragma unroll
    for (int dy = 0; dy < 7; dy++) {
        int y = gy * 7 + dy;
#pragma unroll
        for (int dx = 0; dx < 7; dx++) {
            int x = gx * 7 + dx;
            size_t pix = (size_t)((b * HH + y) * WW + x);
            s += g_H[pix * H1 + j];
        }
    }
    g_Hbar[t * H1 + j] = s * (1.0f / 49.0f);
}

// ---------------- kernel 3: GEMM2 + VQ (8 tokens/block, 256 blocks) ----------------
#define VQ_TOKS 8
#define CBT_LD 257
#define FS_LD 65
#define SMEM_VQ_FLOATS (64*CBT_LD + VQ_TOKS*H1 + VQ_TOKS*FS_LD + KCODES + VQ_TOKS)
#define SMEM_VQ_BYTES (SMEM_VQ_FLOATS * 4)

__global__ __launch_bounds__(256) void k_vq2(const float* __restrict__ w2,
                                             const float* __restrict__ b2,
                                             const float* __restrict__ cb) {
    extern __shared__ float smv[];
    float* cbT   = smv;
    float* hbs   = cbT + 64 * CBT_LD;
    float* fs    = hbs + VQ_TOKS * H1;
    float* cn    = fs + VQ_TOKS * FS_LD;
    float* fnorm = cn + KCODES;

    const int tid = threadIdx.x;
    const int tok0 = blockIdx.x * VQ_TOKS;

    for (int li = tid; li < KCODES * EDIM; li += 256) {
        int c = li >> 6, j = li & 63;
        cbT[j * CBT_LD + c] = cb[li];
    }
    for (int li = tid; li < VQ_TOKS * H1; li += 256)
        hbs[li] = g_Hbar[tok0 * H1 + li];
    __syncthreads();

    {
        float s = 0.0f;
#pragma unroll 8
        for (int j = 0; j < EDIM; j++) {
            float v = cbT[j * CBT_LD + tid];
            s = fmaf(v, v, s);
        }
        cn[tid] = s;
    }

    {
        const int j = tid & 63, tg = tid >> 6;
        float bj = b2[j];
        float acc0 = bj, acc1 = bj;
#pragma unroll 4
        for (int k = 0; k < H1; k++) {
            float wv = __ldg(&w2[k * EDIM + j]);
            acc0 = fmaf(hbs[(tg * 2 + 0) * H1 + k], wv, acc0);
            acc1 = fmaf(hbs[(tg * 2 + 1) * H1 + k], wv, acc1);
        }
        fs[(tg * 2 + 0) * FS_LD + j] = acc0;
        fs[(tg * 2 + 1) * FS_LD + j] = acc1;
    }
    __syncthreads();

    if (tid < VQ_TOKS) {
        float s = 0.0f;
#pragma unroll 8
        for (int j = 0; j < EDIM; j++) {
            float v = fs[tid * FS_LD + j];
            s = fmaf(v, v, s);
        }
        fnorm[tid] = s;
    }
    __syncthreads();

    const int w = tid >> 5, l = tid & 31;
    float dot[8];
#pragma unroll
    for (int i = 0; i < 8; i++) dot[i] = 0.0f;
#pragma unroll 4
    for (int j = 0; j < EDIM; j++) {
        float fj = fs[w * FS_LD + j];
#pragma unroll
        for (int i = 0; i < 8; i++)
            dot[i] = fmaf(fj, cbT[j * CBT_LD + l + 32 * i], dot[i]);
    }
    float bd = 3.4e38f; int bi = 0;
#pragma unroll
    for (int i = 0; i < 8; i++) {
        int c = l + 32 * i;
        float d = fmaf(-2.0f, dot[i], cn[c]);
        if (d < bd) { bd = d; bi = c; }
    }
    for (int off = 16; off > 0; off >>= 1) {
        float od = __shfl_down_sync(0xffffffffu, bd, off);
        int   oi = __shfl_down_sync(0xffffffffu, bi, off);
        if (od < bd || (od == bd && oi < bi)) { bd = od; bi = oi; }
    }
    if (l == 0) {
        int tok = tok0 + w;
        g_idx[tok] = bi;
        atomicAdd(&g_counts[bi], 1);
        atomicAdd(&g_loss, fnorm[w] + bd);
    }
}

// ---------------- kernel 4: perplexity + commitment + indices ----------------
__global__ __launch_bounds__(256) void k_fin(float* __restrict__ out) {
    __shared__ float r[256];
    int tid = threadIdx.x;
    float p = (float)g_counts[tid] * (1.0f / (float)NTOK);
    r[tid] = p * logf(p + 1e-10f);
    __syncthreads();
    for (int s = 128; s > 0; s >>= 1) {
        if (tid < s) r[tid] += r[tid + s];
        __syncthreads();
    }
    if (tid == 0) {
        out[OUT_PPL] = expf(-r[0]);
        out[OUT_CMT] = g_loss * (1.0f / (float)(NTOK * EDIM));
    }
    for (int i = tid; i < NTOK; i += 256) out[OUT_IDX + i] = (float)g_idx[i];
}

// ---------------- kernel 5: decoder MLP (8 tokens per block) ----------------
__global__ __launch_bounds__(256) void k_dec(const float* __restrict__ dw1,
                                             const float* __restrict__ db1,
                                             const float* __restrict__ dw2,
                                             const float* __restrict__ db2,
                                             const float* __restrict__ cb) {
    __shared__ float q[8][EDIM];
    __shared__ float hd[8][H1];
    int tid = threadIdx.x;
    int tb = blockIdx.x * 8;

    for (int li = tid; li < 8 * EDIM; li += 256) {
        int tt = li >> 6, j = li & 63;
        q[tt][j] = cb[g_idx[tb + tt] * EDIM + j];
    }
    __syncthreads();
#pragma unroll
    for (int i = 0; i < 4; i++) {
        int li = tid + i * 256;
        int tt = li >> 7, j = li & 127;
        float s = db1[j];
#pragma unroll 8
        for (int k = 0; k < EDIM; k++) s = fmaf(q[tt][k], dw1[k * H1 + j], s);
        hd[tt][j] = gelu_exact(s);
    }
    __syncthreads();

    float a0[8], a1[8];
#pragma unroll
    for (int tt = 0; tt < 8; tt++) { a0[tt] = 0.0f; a1[tt] = 0.0f; }
#pragma unroll 4
    for (int k = 0; k < H1; k++) {
        float w0 = dw2[k * DIN + tid];
        float w1v = dw2[k * DIN + 256 + tid];
#pragma unroll
        for (int tt = 0; tt < 8; tt++) {
            float h = hd[tt][k];
            a0[tt] = fmaf(h, w0, a0[tt]);
            a1[tt] = fmaf(h, w1v, a1[tt]);
        }
    }
    float bb0 = db2[tid], bb1 = db2[tid + 256];
#pragma unroll
    for (int tt = 0; tt < 8; tt++) {
        g_S[(size_t)(tb + tt) * DIN + tid]       = a0[tt] + bb0;
        g_S[(size_t)(tb + tt) * DIN + 256 + tid] = a1[tt] + bb1;
    }
}

// ---------------- kernel 6: 2x2 -> 14x14 bilinear ----------------
__global__ __launch_bounds__(256) void k_up(float* __restrict__ out) {
    __shared__ float Arow[DIN], Brow[DIN];
    int b = blockIdx.x, y = blockIdx.y;
    int tid = threadIdx.x;

    float sy = (y + 0.5f) * (1.0f / 7.0f) - 0.5f;
    int iy0 = (int)floorf(sy);
    float fy = sy - (float)iy0;
    int y0 = min(max(iy0, 0), 1);
    int y1 = min(max(iy0 + 1, 0), 1);

    const float* S0a = &g_S[(size_t)(b * 4 + y0 * 2 + 0) * DIN];
    const float* S1a = &g_S[(size_t)(b * 4 + y1 * 2 + 0) * DIN];
    const float* S0b = &g_S[(size_t)(b * 4 + y0 * 2 + 1) * DIN];
    const float* S1b = &g_S[(size_t)(b * 4 + y1 * 2 + 1) * DIN];
    float wy0 = 1.0f - fy;
    for (int c = tid; c < DIN; c += 256) {
        Arow[c] = wy0 * S0a[c] + fy * S1a[c];
        Brow[c] = wy0 * S0b[c] + fy * S1b[c];
    }
    __syncthreads();

#pragma unroll
    for (int x = 0; x < 14; x++) {
        float sx = (x + 0.5f) * (1.0f / 7.0f) - 0.5f;
        int ix0 = (int)floorf(sx);
        float fx = sx - (float)ix0;
        int x0 = min(max(ix0, 0), 1);
        int x1 = min(max(ix0 + 1, 0), 1);
        float wx0 = 1.0f - fx;
        float* o = out + ((size_t)((b * HH + y) * WW + x)) * DIN;
        for (int c = tid; c < DIN; c += 256) {
            float v0 = x0 ? Brow[c] : Arow[c];
            float v1 = x1 ? Brow[c] : Arow[c];
            o[c] = wx0 * v0 + fx * v1;
        }
    }
}

// ---------------- host: tensor-map encode via dlopen (no libcuda link dep) ----------------
typedef CUresult (*encode_fn_t)(CUtensorMap*, CUtensorMapDataType, cuuint32_t, void*,
                                const cuuint64_t*, const cuuint64_t*, const cuuint32_t*,
                                const cuuint32_t*, CUtensorMapInterleave, CUtensorMapSwizzle,
                                CUtensorMapL2promotion, CUtensorMapFloatOOBfill);

extern "C" void kernel_launch(void* const* d_in, const int* in_sizes, int n_in,
                              void* d_out, int out_size) {
    const float* t0  = (const float*)d_in[0];
    const float* t1  = (const float*)d_in[1];
    const float* ew1 = (const float*)d_in[2];
    const float* eb1 = (const float*)d_in[3];
    const float* ew2 = (const float*)d_in[4];
    const float* eb2 = (const float*)d_in[5];
    const float* dw1 = (const float*)d_in[6];
    const float* db1 = (const float*)d_in[7];
    const float* dw2 = (const float*)d_in[8];
    const float* db2 = (const float*)d_in[9];
    const float* cb  = (const float*)d_in[10];
    float* out = (float*)d_out;

    // encode TMA descriptors (host-side, graph-capture-safe)
    CUtensorMap mapT0, mapT1;
    bool use_tma = false;
    {
        void* h = dlopen("libcuda.so.1", RTLD_LAZY | RTLD_GLOBAL);
        if (!h) h = dlopen("libcuda.so", RTLD_LAZY | RTLD_GLOBAL);
        if (h) {
            encode_fn_t fn = (encode_fn_t)dlsym(h, "cuTensorMapEncodeTiled");
            if (fn) {
                cuuint64_t dims[2]    = {(cuuint64_t)DIN, (cuuint64_t)NPIX};
                cuuint64_t strides[1] = {(cuuint64_t)DIN * 4};
                cuuint32_t box[2]     = {64, 128};
                cuuint32_t es[2]      = {1, 1};
                CUresult r0 = fn(&mapT0, CU_TENSOR_MAP_DATA_TYPE_FLOAT32, 2, (void*)t0,
                                 dims, strides, box, es, CU_TENSOR_MAP_INTERLEAVE_NONE,
                                 CU_TENSOR_MAP_SWIZZLE_NONE, CU_TENSOR_MAP_L2_PROMOTION_L2_128B,
                                 CU_TENSOR_MAP_FLOAT_OOB_FILL_NONE);
                CUresult r1 = fn(&mapT1, CU_TENSOR_MAP_DATA_TYPE_FLOAT32, 2, (void*)t1,
                                 dims, strides, box, es, CU_TENSOR_MAP_INTERLEAVE_NONE,
                                 CU_TENSOR_MAP_SWIZZLE_NONE, CU_TENSOR_MAP_L2_PROMOTION_L2_128B,
                                 CU_TENSOR_MAP_FLOAT_OOB_FILL_NONE);
                use_tma = (r0 == CUDA_SUCCESS && r1 == CUDA_SUCCESS);
            }
        }
    }

    cudaFuncSetAttribute(k_enc1_tma, cudaFuncAttributeMaxDynamicSharedMemorySize, ENC2_SM_BYTES);
    cudaFuncSetAttribute(k_enc1_ldg, cudaFuncAttributeMaxDynamicSharedMemorySize, ENC_SM_BYTES);
    cudaFuncSetAttribute(k_vq2, cudaFuncAttributeMaxDynamicSharedMemorySize, SMEM_VQ_BYTES);

    k_init<<<1, 256>>>();
    k_prep<<<DIN * H1 / 256, 256>>>(ew1);
    if (use_tma)
        k_enc1_tma<<<NPIX / 128, 256, ENC2_SM_BYTES>>>(mapT0, mapT1, eb1);
    else
        k_enc1_ldg<<<NPIX / 128, 256, ENC_SM_BYTES>>>(t0, t1, eb1);
    k_pool<<<NTOK, 128>>>();
    k_vq2<<<NTOK / VQ_TOKS, 256, SMEM_VQ_BYTES>>>(ew2, eb2, cb);
    k_fin<<<1, 256>>>(out);
    k_dec<<<NTOK / 8, 256>>>(dw1, db1, dw2, db2, cb);
    k_up<<<dim3(BATCH, HH), 256>>>(out);
}

// round 11
// speedup vs baseline: 1.0577x; 1.0577x over previous
#include <cuda_runtime.h>
#include <cuda_bf16.h>
#include <math.h>
#include <stdint.h>

// ---------------- problem constants ----------------
#define BATCH 512
#define HH 14
#define WW 14
#define DIN 512
#define EDIM 64
#define KCODES 256
#define NPIX (BATCH*HH*WW)          // 100352
#define NTOK (BATCH*4)              // 2048
#define H1 128                      // 2*EDIM

#define OUT_PPL ((size_t)NPIX*DIN)
#define OUT_CMT (OUT_PPL+1)
#define OUT_IDX (OUT_PPL+2)

// ---------------- scratch (static device memory; no allocations) ----------------
__device__ float g_Hbar[NTOK*H1];           // pooled SUMS (scaled by 1/49 in k_vq2)
__device__ float g_S[NTOK*DIN];
__device__ int   g_idx[NTOK];
__device__ int   g_counts[KCODES];
__device__ float g_loss;
// W1^T split into bf16 hi/lo: [n=128][k=512]
__device__ __nv_bfloat16 g_w1t_hi[H1*DIN];
__device__ __nv_bfloat16 g_w1t_lo[H1*DIN];

__device__ __forceinline__ float gelu_exact(float x) {
    return 0.5f * x * (1.0f + erff(x * 0.70710678118654752440f));
}

__device__ __forceinline__ uint32_t smem_u32(const void* p) {
    uint32_t a;
    asm("{ .reg .u64 t; cvta.to.shared.u64 t, %1; cvt.u32.u64 %0, t; }" : "=r"(a) : "l"(p));
    return a;
}

// baseline-PTX tensor ops (valid on plain sm_103 — no 'a' features)
__device__ __forceinline__ void ldsm_x4(uint32_t* r, uint32_t addr) {
    asm volatile("ldmatrix.sync.aligned.m8n8.x4.shared.b16 {%0,%1,%2,%3}, [%4];"
                 : "=r"(r[0]), "=r"(r[1]), "=r"(r[2]), "=r"(r[3]) : "r"(addr));
}
__device__ __forceinline__ void mma_bf16(float* d, const uint32_t* a, const uint32_t* b) {
    asm volatile("mma.sync.aligned.m16n8k16.row.col.f32.bf16.bf16.f32 "
                 "{%0,%1,%2,%3}, {%4,%5,%6,%7}, {%8,%9}, {%0,%1,%2,%3};"
                 : "+f"(d[0]), "+f"(d[1]), "+f"(d[2]), "+f"(d[3])
                 : "r"(a[0]), "r"(a[1]), "r"(a[2]), "r"(a[3]), "r"(b[0]), "r"(b[1]));
}
__device__ __forceinline__ uint32_t pk_bf16(__nv_bfloat16 a, __nv_bfloat16 b) {
    return (uint32_t)__bfloat16_as_ushort(a) | ((uint32_t)__bfloat16_as_ushort(b) << 16);
}
__device__ __forceinline__ void cp_async16(uint32_t dst, const void* src) {
    asm volatile("cp.async.ca.shared.global [%0], [%1], 16;" :: "r"(dst), "l"(src) : "memory");
}
#define CP_COMMIT()  asm volatile("cp.async.commit_group;" ::: "memory")
#define CP_WAIT0()   asm volatile("cp.async.wait_group 0;" ::: "memory")

// ---------------- kernel 0: zero accumulators ----------------
__global__ void k_init() {
    int t = threadIdx.x;
    if (t < KCODES) g_counts[t] = 0;
    if (t == 0) g_loss = 0.0f;
}

// ---------------- kernel 0a: zero Hbar accumulation buffer ----------------
__global__ __launch_bounds__(256) void k_zeroH() {
    int i = blockIdx.x * 256 + threadIdx.x;     // 256 blocks x 256 thr x 4 floats
    *(float4*)&g_Hbar[i * 4] = make_float4(0.f, 0.f, 0.f, 0.f);
}

// ---------------- kernel 0b: pre-split W1^T into bf16 hi/lo ----------------
__global__ __launch_bounds__(256) void k_prep(const float* __restrict__ w1) {
    int idx = blockIdx.x * 256 + threadIdx.x;   // over 512*128
    int k = idx >> 7, n = idx & 127;
    float v = w1[idx];
    __nv_bfloat16 hi = __float2bfloat16(v);
    __nv_bfloat16 lo = __float2bfloat16(v - __bfloat162float(hi));
    g_w1t_hi[n * DIN + k] = hi;
    g_w1t_lo[n * DIN + k] = lo;
}

// ---------------- kernel 1: delta -> split-bf16 HMMA GEMM -> GELU -> fused 7x7 pool ----
// Block: 128 pixels x 128 outputs. K=512 in 8 chunks of 64 via smem.
// 8 warps 4x2; warp tile 32x64. After compute, GELU tile lands in smem
// (pitch 130 fp32) and is pooled into g_Hbar via global atomics.
#define SM_AHI 0
#define SM_ALO (128*144)
#define SM_BHI (2*128*144)
#define SM_BLO (3*128*144)
#define ENC_SM_BYTES (4*128*144)   // 73728; H tile reuse needs 128*130*4=66560 <= this
#define HS_PITCH 130

__global__ __launch_bounds__(256, 2) void k_enc1(const float* __restrict__ t0,
                                                 const float* __restrict__ t1,
                                                 const float* __restrict__ b1) {
    extern __shared__ char sm[];
    const uint32_t smb = smem_u32(sm);
    float* Hs = (float*)sm;                       // [128][130] after compute
    const int tid = threadIdx.x;
    const int wid = tid >> 5, l = tid & 31;
    const int wm = wid & 3, wn = wid >> 2;
    const int p0 = blockIdx.x * 128;

    float acc[2][8][4];
#pragma unroll
    for (int rt = 0; rt < 2; rt++)
#pragma unroll
        for (int nt = 0; nt < 8; nt++)
#pragma unroll
            for (int q = 0; q < 4; q++) acc[rt][nt][q] = 0.0f;

    const uint32_t a_row = (uint32_t)(wm * 32 + (l & 15));
    const uint32_t a_kof = (uint32_t)((l >> 4) * 16);
    const uint32_t b_row4 = (uint32_t)(wn * 64 + ((l >> 4) << 3) + (l & 7));
    const uint32_t b_k4   = (uint32_t)(((l >> 3) & 1) * 16);

    for (int c = 0; c < 8; c++) {
        const int kc = c * 64;
        if (c) __syncthreads();
#pragma unroll
        for (int it = 0; it < 4; it++) {
            int i = tid + it * 256;
            int n = i >> 3, g = i & 7;
            uint32_t off = (uint32_t)(n * 144 + g * 16);
            cp_async16(smb + SM_BHI + off, g_w1t_hi + n * DIN + kc + g * 8);
            cp_async16(smb + SM_BLO + off, g_w1t_lo + n * DIN + kc + g * 8);
        }
        CP_COMMIT();
#pragma unroll
        for (int half = 0; half < 4; half++) {
            float4 v1[2], v0[2];
            int rows[2], gs[2];
#pragma unroll
            for (int u = 0; u < 2; u++) {
                int i = tid + (half * 2 + u) * 256;
                rows[u] = i >> 4; gs[u] = i & 15;
                size_t gaddr = (size_t)(p0 + rows[u]) * DIN + kc + gs[u] * 4;
                v1[u] = *(const float4*)(t1 + gaddr);
                v0[u] = *(const float4*)(t0 + gaddr);
            }
#pragma unroll
            for (int u = 0; u < 2; u++) {
                float d0 = v1[u].x - v0[u].x, d1 = v1[u].y - v0[u].y,
                      d2 = v1[u].z - v0[u].z, d3 = v1[u].w - v0[u].w;
                __nv_bfloat16 h0 = __float2bfloat16(d0), h1 = __float2bfloat16(d1),
                              h2 = __float2bfloat16(d2), h3 = __float2bfloat16(d3);
                __nv_bfloat16 e0 = __float2bfloat16(d0 - __bfloat162float(h0));
                __nv_bfloat16 e1 = __float2bfloat16(d1 - __bfloat162float(h1));
                __nv_bfloat16 e2 = __float2bfloat16(d2 - __bfloat162float(h2));
                __nv_bfloat16 e3 = __float2bfloat16(d3 - __bfloat162float(h3));
                uint32_t off = (uint32_t)(rows[u] * 144 + gs[u] * 8);
                *(uint2*)(sm + SM_AHI + off) = make_uint2(pk_bf16(h0, h1), pk_bf16(h2, h3));
                *(uint2*)(sm + SM_ALO + off) = make_uint2(pk_bf16(e0, e1), pk_bf16(e2, e3));
            }
        }
        CP_WAIT0();
        __syncthreads();
#pragma unroll
        for (int ks = 0; ks < 4; ks++) {
            uint32_t ahi[2][4], alo[2][4];
#pragma unroll
            for (int rt = 0; rt < 2; rt++) {
                uint32_t aoff = (a_row + rt * 16) * 144 + ks * 32 + a_kof;
                ldsm_x4(ahi[rt], smb + SM_AHI + aoff);
                ldsm_x4(alo[rt], smb + SM_ALO + aoff);
            }
#pragma unroll
            for (int ntp = 0; ntp < 4; ntp++) {
                uint32_t boff = (b_row4 + ntp * 16) * 144 + ks * 32 + b_k4;
                uint32_t bhi[4], blo[4];
                ldsm_x4(bhi, smb + SM_BHI + boff);
                ldsm_x4(blo, smb + SM_BLO + boff);
#pragma unroll
                for (int h = 0; h < 2; h++) {
                    int nt = ntp * 2 + h;
#pragma unroll
                    for (int rt = 0; rt < 2; rt++) {
                        mma_bf16(acc[rt][nt], ahi[rt], bhi + 2 * h);
                        mma_bf16(acc[rt][nt], ahi[rt], blo + 2 * h);
                        mma_bf16(acc[rt][nt], alo[rt], bhi + 2 * h);
                    }
                }
            }
        }
    }

    // ---- epilogue: bias + GELU into smem tile (reuses A/B tile space) ----
    float2 bias[8];
#pragma unroll
    for (int nt = 0; nt < 8; nt++) {
        int cc = wn * 64 + nt * 8 + 2 * (l & 3);
        bias[nt] = make_float2(__ldg(&b1[cc]), __ldg(&b1[cc + 1]));
    }
    __syncthreads();     // all ldsm consumers done before overwriting tiles
#pragma unroll
    for (int rt = 0; rt < 2; rt++) {
        int rl = wm * 32 + rt * 16 + (l >> 2);    // local row
#pragma unroll
        for (int nt = 0; nt < 8; nt++) {
            int cc = wn * 64 + nt * 8 + 2 * (l & 3);
            float2 o0, o1;
            o0.x = gelu_exact(acc[rt][nt][0] + bias[nt].x);
            o0.y = gelu_exact(acc[rt][nt][1] + bias[nt].y);
            o1.x = gelu_exact(acc[rt][nt][2] + bias[nt].x);
            o1.y = gelu_exact(acc[rt][nt][3] + bias[nt].y);
            *(float2*)&Hs[rl * HS_PITCH + cc]       = o0;
            *(float2*)&Hs[(rl + 8) * HS_PITCH + cc] = o1;
        }
    }
    __syncthreads();

    // ---- fused 7x7 pooling: 8 token slots x 128 channels, 4 pairs/thread ----
    const int b0 = p0 / 196;
#pragma unroll
    for (int i = 0; i < 4; i++) {
        int pair = tid + i * 256;                 // 0..1023
        int slot = pair >> 7, col = pair & 127;   // slot: (db,ty,tx)
        int db = slot >> 2, ty = (slot >> 1) & 1, tx = slot & 1;
        int b = b0 + db;
        int base = b * 196 + ty * 98 + tx * 7 - p0;   // local row of (dy=0,dx=0)
        float s = 0.0f;
        int hit = 0;
#pragma unroll
        for (int dy = 0; dy < 7; dy++) {
            int rs = base + dy * 14;
            int lo = rs < 0 ? 0 : rs;
            int hi = rs + 7 > 128 ? 128 : rs + 7;
            for (int r = lo; r < hi; r++) { s += Hs[r * HS_PITCH + col]; hit = 1; }
        }
        if (hit) atomicAdd(&g_Hbar[(size_t)(b * 4 + ty * 2 + tx) * H1 + col], s);
    }
}

// ---------------- kernel 3: GEMM2 + VQ (8 tokens/block, 256 blocks) ----------------
#define VQ_TOKS 8
#define CBT_LD 257
#define FS_LD 65
#define SMEM_VQ_FLOATS (64*CBT_LD + VQ_TOKS*H1 + VQ_TOKS*FS_LD + KCODES + VQ_TOKS)
#define SMEM_VQ_BYTES (SMEM_VQ_FLOATS * 4)

__global__ __launch_bounds__(256) void k_vq2(const float* __restrict__ w2,
                                             const float* __restrict__ b2,
                                             const float* __restrict__ cb) {
    extern __shared__ float smv[];
    float* cbT   = smv;
    float* hbs   = cbT + 64 * CBT_LD;
    float* fs    = hbs + VQ_TOKS * H1;
    float* cn    = fs + VQ_TOKS * FS_LD;
    float* fnorm = cn + KCODES;

    const int tid = threadIdx.x;
    const int tok0 = blockIdx.x * VQ_TOKS;

    for (int li = tid; li < KCODES * EDIM; li += 256) {
        int c = li >> 6, j = li & 63;
        cbT[j * CBT_LD + c] = cb[li];
    }
    for (int li = tid; li < VQ_TOKS * H1; li += 256)
        hbs[li] = g_Hbar[tok0 * H1 + li] * (1.0f / 49.0f);   // pooled sums -> mean
    __syncthreads();

    {
        float s = 0.0f;
#pragma unroll 8
        for (int j = 0; j < EDIM; j++) {
            float v = cbT[j * CBT_LD + tid];
            s = fmaf(v, v, s);
        }
        cn[tid] = s;
    }

    {
        const int j = tid & 63, tg = tid >> 6;
        float bj = b2[j];
        float acc0 = bj, acc1 = bj;
#pragma unroll 4
        for (int k = 0; k < H1; k++) {
            float wv = __ldg(&w2[k * EDIM + j]);
            acc0 = fmaf(hbs[(tg * 2 + 0) * H1 + k], wv, acc0);
            acc1 = fmaf(hbs[(tg * 2 + 1) * H1 + k], wv, acc1);
        }
        fs[(tg * 2 + 0) * FS_LD + j] = acc0;
        fs[(tg * 2 + 1) * FS_LD + j] = acc1;
    }
    __syncthreads();

    if (tid < VQ_TOKS) {
        float s = 0.0f;
#pragma unroll 8
        for (int j = 0; j < EDIM; j++) {
            float v = fs[tid * FS_LD + j];
            s = fmaf(v, v, s);
        }
        fnorm[tid] = s;
    }
    __syncthreads();

    const int w = tid >> 5, l = tid & 31;
    float dot[8];
#pragma unroll
    for (int i = 0; i < 8; i++) dot[i] = 0.0f;
#pragma unroll 4
    for (int j = 0; j < EDIM; j++) {
        float fj = fs[w * FS_LD + j];
#pragma unroll
        for (int i = 0; i < 8; i++)
            dot[i] = fmaf(fj, cbT[j * CBT_LD + l + 32 * i], dot[i]);
    }
    float bd = 3.4e38f; int bi = 0;
#pragma unroll
    for (int i = 0; i < 8; i++) {
        int c = l + 32 * i;
        float d = fmaf(-2.0f, dot[i], cn[c]);
        if (d < bd) { bd = d; bi = c; }
    }
    for (int off = 16; off > 0; off >>= 1) {
        float od = __shfl_down_sync(0xffffffffu, bd, off);
        int   oi = __shfl_down_sync(0xffffffffu, bi, off);
        if (od < bd || (od == bd && oi < bi)) { bd = od; bi = oi; }
    }
    if (l == 0) {
        int tok = tok0 + w;
        g_idx[tok] = bi;
        atomicAdd(&g_counts[bi], 1);
        atomicAdd(&g_loss, fnorm[w] + bd);
    }
}

// ---------------- kernel 4: perplexity + commitment + indices ----------------
__global__ __launch_bounds__(256) void k_fin(float* __restrict__ out) {
    __shared__ float r[256];
    int tid = threadIdx.x;
    float p = (float)g_counts[tid] * (1.0f / (float)NTOK);
    r[tid] = p * logf(p + 1e-10f);
    __syncthreads();
    for (int s = 128; s > 0; s >>= 1) {
        if (tid < s) r[tid] += r[tid + s];
        __syncthreads();
    }
    if (tid == 0) {
        out[OUT_PPL] = expf(-r[0]);
        out[OUT_CMT] = g_loss * (1.0f / (float)(NTOK * EDIM));
    }
    for (int i = tid; i < NTOK; i += 256) out[OUT_IDX + i] = (float)g_idx[i];
}

// ---------------- kernel 5: decoder MLP (8 tokens per block) ----------------
__global__ __launch_bounds__(256) void k_dec(const float* __restrict__ dw1,
                                             const float* __restrict__ db1,
                                             const float* __restrict__ dw2,
                                             const float* __restrict__ db2,
                                             const float* __restrict__ cb) {
    __shared__ float q[8][EDIM];
    __shared__ float hd[8][H1];
    int tid = threadIdx.x;
    int tb = blockIdx.x * 8;

    for (int li = tid; li < 8 * EDIM; li += 256) {
        int tt = li >> 6, j = li & 63;
        q[tt][j] = cb[g_idx[tb + tt] * EDIM + j];
    }
    __syncthreads();
#pragma unroll
    for (int i = 0; i < 4; i++) {
        int li = tid + i * 256;
        int tt = li >> 7, j = li & 127;
        float s = db1[j];
#pragma unroll 8
        for (int k = 0; k < EDIM; k++) s = fmaf(q[tt][k], dw1[k * H1 + j], s);
        hd[tt][j] = gelu_exact(s);
    }
    __syncthreads();

    float a0[8], a1[8];
#pragma unroll
    for (int tt = 0; tt < 8; tt++) { a0[tt] = 0.0f; a1[tt] = 0.0f; }
#pragma unroll 4
    for (int k = 0; k < H1; k++) {
        float w0 = dw2[k * DIN + tid];
        float w1v = dw2[k * DIN + 256 + tid];
#pragma unroll
        for (int tt = 0; tt < 8; tt++) {
            float h = hd[tt][k];
            a0[tt] = fmaf(h, w0, a0[tt]);
            a1[tt] = fmaf(h, w1v, a1[tt]);
        }
    }
    float bb0 = db2[tid], bb1 = db2[tid + 256];
#pragma unroll
    for (int tt = 0; tt < 8; tt++) {
        g_S[(size_t)(tb + tt) * DIN + tid]       = a0[tt] + bb0;
        g_S[(size_t)(tb + tt) * DIN + 256 + tid] = a1[tt] + bb1;
    }
}

// ---------------- kernel 6: 2x2 -> 14x14 bilinear ----------------
__global__ __launch_bounds__(256) void k_up(float* __restrict__ out) {
    __shared__ float Arow[DIN], Brow[DIN];
    int b = blockIdx.x, y = blockIdx.y;
    int tid = threadIdx.x;

    float sy = (y + 0.5f) * (1.0f / 7.0f) - 0.5f;
    int iy0 = (int)floorf(sy);
    float fy = sy - (float)iy0;
    int y0 = min(max(iy0, 0), 1);
    int y1 = min(max(iy0 + 1, 0), 1);

    const float* S0a = &g_S[(size_t)(b * 4 + y0 * 2 + 0) * DIN];
    const float* S1a = &g_S[(size_t)(b * 4 + y1 * 2 + 0) * DIN];
    const float* S0b = &g_S[(size_t)(b * 4 + y0 * 2 + 1) * DIN];
    const float* S1b = &g_S[(size_t)(b * 4 + y1 * 2 + 1) * DIN];
    float wy0 = 1.0f - fy;
    for (int c = tid; c < DIN; c += 256) {
        Arow[c] = wy0 * S0a[c] + fy * S1a[c];
        Brow[c] = wy0 * S0b[c] + fy * S1b[c];
    }
    __syncthreads();

#pragma unroll
    for (int x = 0; x < 14; x++) {
        float sx = (x + 0.5f) * (1.0f / 7.0f) - 0.5f;
        int ix0 = (int)floorf(sx);
        float fx = sx - (float)ix0;
        int x0 = min(max(ix0, 0), 1);
        int x1 = min(max(ix0 + 1, 0), 1);
        float wx0 = 1.0f - fx;
        float* o = out + ((size_t)((b * HH + y) * WW + x)) * DIN;
        for (int c = tid; c < DIN; c += 256) {
            float v0 = x0 ? Brow[c] : Arow[c];
            float v1 = x1 ? Brow[c] : Arow[c];
            o[c] = wx0 * v0 + fx * v1;
        }
    }
}

// ---------------- launch ----------------
extern "C" void kernel_launch(void* const* d_in, const int* in_sizes, int n_in,
                              void* d_out, int out_size) {
    const float* t0  = (const float*)d_in[0];
    const float* t1  = (const float*)d_in[1];
    const float* ew1 = (const float*)d_in[2];
    const float* eb1 = (const float*)d_in[3];
    const float* ew2 = (const float*)d_in[4];
    const float* eb2 = (const float*)d_in[5];
    const float* dw1 = (const float*)d_in[6];
    const float* db1 = (const float*)d_in[7];
    const float* dw2 = (const float*)d_in[8];
    const float* db2 = (const float*)d_in[9];
    const float* cb  = (const float*)d_in[10];
    float* out = (float*)d_out;

    cudaFuncSetAttribute(k_enc1, cudaFuncAttributeMaxDynamicSharedMemorySize, ENC_SM_BYTES);
    cudaFuncSetAttribute(k_vq2, cudaFuncAttributeMaxDynamicSharedMemorySize, SMEM_VQ_BYTES);

    k_init<<<1, 256>>>();                                   // launch 1
    k_zeroH<<<NTOK * H1 / 1024, 256>>>();                   // launch 2
    k_prep<<<DIN * H1 / 256, 256>>>(ew1);                   // launch 3
    k_enc1<<<NPIX / 128, 256, ENC_SM_BYTES>>>(t0, t1, eb1); // launch 4 (ncu target)
    k_vq2<<<NTOK / VQ_TOKS, 256, SMEM_VQ_BYTES>>>(ew2, eb2, cb);
    k_fin<<<1, 256>>>(out);
    k_dec<<<NTOK / 8, 256>>>(dw1, db1, dw2, db2, cb);
    k_up<<<dim3(BATCH, HH), 256>>>(out);
}